// round 11
// baseline (speedup 1.0000x reference)
#include <cuda_runtime.h>
#include <math.h>

// Problem constants
#define BATCH 8
#define NNODES 4096
#define DIN0 64
#define DHID 128
#define DOUT0 64
#define CAP 512          // max neighbors per row (mean ~82 at 2% density; P(>512)~0)

#define LOG2E 1.4426950408889634f

// ---------------- static device scratch (no allocations allowed) -------------
// d_h1 aliasing: [0:2M) = y1 (layer1 score vecs), [2M:4M) = c (layer1 agg out);
// after y1 dies, [0:2M) is reused for h2 (layer2 linear out).
__device__ int   d_col[NNODES * CAP + 8];        // +8 pad: masked batch overread
__device__ int   d_deg[NNODES];
__device__ float d_h1[BATCH * NNODES * DHID];    // 16 MB, aliased as above
__device__ float d_t1[BATCH * NNODES * DHID];    // 16 MB
__device__ float d_wt1[DIN0 * DHID];             // W1^T  [k][c]
__device__ float d_wt2[DHID * DOUT0];            // W2^T  [k][c]
__device__ float d_g1[DIN0 * DIN0];              // G = W1^T W1 (64x64)

// ---------------- weight transposes + G = W1^T W1 (fused) --------------------
__global__ void prep_kernel(const float* __restrict__ W1, const float* __restrict__ W2) {
    int i = blockIdx.x * blockDim.x + threadIdx.x;
    if (i < DHID * DIN0) {            // W1: [128][64] -> wt1[k*128 + c]
        int c = i / DIN0, k = i % DIN0;
        d_wt1[k * DHID + c] = W1[i];
    }
    if (i < DOUT0 * DHID) {           // W2: [64][128] -> wt2[k*64 + c]
        int c = i / DHID, k = i % DHID;
        d_wt2[k * DOUT0 + c] = W2[i];
    }
    if (i < DIN0 * DIN0) {            // G[e][d] = sum_h W1[h][d] * W1[h][e]
        int d = i & 63, e = i >> 6;
        float s = 0.0f;
#pragma unroll 4
        for (int h = 0; h < DHID; h++)
            s = fmaf(W1[h * DIN0 + d], W1[h * DIN0 + e], s);
        d_g1[e * DIN0 + d] = s;
    }
}

// ---------------- build CSR from dense binary graph (order-preserving) -------
__global__ void build_csr_kernel(const float* __restrict__ graph) {
    int row  = blockIdx.x * (blockDim.x >> 5) + (threadIdx.x >> 5);
    int lane = threadIdx.x & 31;
    if (row >= NNODES) return;
    const float* g = graph + (size_t)row * NNODES;
    int cnt = 0;
    for (int base = 0; base < NNODES; base += 32) {
        float v = g[base + lane];
        unsigned ball = __ballot_sync(0xffffffffu, v != 0.0f);
        int prefix = __popc(ball & ((1u << lane) - 1u));
        if (v != 0.0f) {
            int pos = cnt + prefix;
            if (pos < CAP) d_col[row * CAP + pos] = base + lane;
        }
        cnt += __popc(ball);
    }
    if (lane == 0) d_deg[row] = (cnt < CAP) ? cnt : CAP;
}

// ---------------- linear body: out[r][c] = sum_k x[r][k]*Wt[k][c] (+b, relu) -
// RPB=8 rows/block -> 4096 blocks -> high occupancy (was grid-starved at RPB=32).
template <int DIN, int DOUT, bool HAS_BIAS, bool RELU>
__device__ __forceinline__ void lin_body(const float* __restrict__ x,
                                         const float* __restrict__ wt,
                                         const float* __restrict__ bias,
                                         float* __restrict__ out) {
    constexpr int RPB = 8;
    __shared__ float xs[RPB * DIN];
    long base = (long)blockIdx.x * RPB;
    const float4* xg  = (const float4*)(x + base * DIN);
    float4*       xs4 = (float4*)xs;
    for (int i = threadIdx.x; i < RPB * DIN / 4; i += blockDim.x) xs4[i] = xg[i];
    __syncthreads();

    int c = threadIdx.x;   // blockDim == DOUT
    float b = HAS_BIAS ? bias[c] : 0.0f;
    float acc[RPB];
#pragma unroll
    for (int r = 0; r < RPB; r++) acc[r] = 0.0f;

    for (int k = 0; k < DIN; k += 4) {
        float w0 = wt[(k + 0) * DOUT + c];
        float w1 = wt[(k + 1) * DOUT + c];
        float w2 = wt[(k + 2) * DOUT + c];
        float w3 = wt[(k + 3) * DOUT + c];
#pragma unroll
        for (int r = 0; r < RPB; r++) {
            float4 xv = *(const float4*)&xs[r * DIN + k];
            acc[r] = fmaf(xv.x, w0, fmaf(xv.y, w1, fmaf(xv.z, w2, fmaf(xv.w, w3, acc[r]))));
        }
    }
#pragma unroll
    for (int r = 0; r < RPB; r++) {
        float o = acc[r] + b;
        if (RELU) o = fmaxf(o, 0.0f);
        out[(base + r) * DOUT + c] = o;
    }
}

__global__ void y1_kernel(const float* __restrict__ x) {          // y1 = x @ G
    lin_body<DIN0, DIN0, false, false>(x, d_g1, nullptr, d_h1);
}
__global__ void postlin_kernel(const float* __restrict__ b1) {    // t1 = relu(c@W1^T+b1)
    lin_body<DIN0, DHID, true, true>(d_h1 + BATCH * NNODES * DIN0, d_wt1, b1, d_t1);
}
__global__ void lin2_kernel() {                                   // h2 = t1 @ W2^T
    lin_body<DHID, DOUT0, false, false>(d_t1, d_wt2, nullptr, d_h1);
}

// ---------------- 8-neighbor batch: load, dot, merged reduce, softmax update -
template <bool MASKED>
__device__ __forceinline__ void agg_batch(const int* __restrict__ cols, int i, int rem,
                                          const float* __restrict__ hb, unsigned loff,
                                          float f0, float f1,
                                          float& M, float& Z, float& a0, float& a1) {
    const unsigned FULL = 0xffffffffu;
    int lane = threadIdx.x & 31;
    int4 ca = *(const int4*)(cols + i);
    int4 cb = *(const int4*)(cols + i + 4);
    float2 g0 = *(const float2*)(hb + (((unsigned)ca.x << 6) + loff));
    float2 g1 = *(const float2*)(hb + (((unsigned)ca.y << 6) + loff));
    float2 g2 = *(const float2*)(hb + (((unsigned)ca.z << 6) + loff));
    float2 g3 = *(const float2*)(hb + (((unsigned)ca.w << 6) + loff));
    float2 g4 = *(const float2*)(hb + (((unsigned)cb.x << 6) + loff));
    float2 g5 = *(const float2*)(hb + (((unsigned)cb.y << 6) + loff));
    float2 g6 = *(const float2*)(hb + (((unsigned)cb.z << 6) + loff));
    float2 g7 = *(const float2*)(hb + (((unsigned)cb.w << 6) + loff));

    float p0 = fmaf(f0, g0.x, f1 * g0.y);
    float p1 = fmaf(f0, g1.x, f1 * g1.y);
    float p2 = fmaf(f0, g2.x, f1 * g2.y);
    float p3 = fmaf(f0, g3.x, f1 * g3.y);
    float p4 = fmaf(f0, g4.x, f1 * g4.y);
    float p5 = fmaf(f0, g5.x, f1 * g5.y);
    float p6 = fmaf(f0, g6.x, f1 * g6.y);
    float p7 = fmaf(f0, g7.x, f1 * g7.y);

    // merged 8-way warp reduction: 9 SHFL-chain + 8 broadcasts = 17 SHFLs
    float qA = (lane & 16) ? p1 : p0, tA = (lane & 16) ? p0 : p1;
    qA += __shfl_xor_sync(FULL, tA, 16);
    float qB = (lane & 16) ? p3 : p2, tB = (lane & 16) ? p2 : p3;
    qB += __shfl_xor_sync(FULL, tB, 16);
    float qC = (lane & 16) ? p5 : p4, tC = (lane & 16) ? p4 : p5;
    qC += __shfl_xor_sync(FULL, tC, 16);
    float qD = (lane & 16) ? p7 : p6, tD = (lane & 16) ? p6 : p7;
    qD += __shfl_xor_sync(FULL, tD, 16);
    float rA = (lane & 8) ? qB : qA, rAt = (lane & 8) ? qA : qB;
    rA += __shfl_xor_sync(FULL, rAt, 8);
    float rB = (lane & 8) ? qD : qC, rBt = (lane & 8) ? qC : qD;
    rB += __shfl_xor_sync(FULL, rBt, 8);
    float u = (lane & 4) ? rB : rA, ut = (lane & 4) ? rA : rB;
    u += __shfl_xor_sync(FULL, ut, 4);
    u += __shfl_xor_sync(FULL, u, 2);
    u += __shfl_xor_sync(FULL, u, 1);
    // group-of-4 ownership: 0:p0 4:p4 8:p2 12:p6 16:p1 20:p5 24:p3 28:p7
    float d0 = __shfl_sync(FULL, u, 0);
    float d1 = __shfl_sync(FULL, u, 16);
    float d2 = __shfl_sync(FULL, u, 8);
    float d3 = __shfl_sync(FULL, u, 24);
    float d4 = __shfl_sync(FULL, u, 4);
    float d5 = __shfl_sync(FULL, u, 20);
    float d6 = __shfl_sync(FULL, u, 12);
    float d7 = __shfl_sync(FULL, u, 28);

    if (MASKED) {                       // only last batch; rem >= 1
        if (rem < 2) d1 = -INFINITY;
        if (rem < 3) d2 = -INFINITY;
        if (rem < 4) d3 = -INFINITY;
        if (rem < 5) d4 = -INFINITY;
        if (rem < 6) d5 = -INFINITY;
        if (rem < 7) d6 = -INFINITY;
        if (rem < 8) d7 = -INFINITY;
    }

    float bm = fmaxf(fmaxf(fmaxf(d0, d1), fmaxf(d2, d3)),
                     fmaxf(fmaxf(d4, d5), fmaxf(d6, d7)));
    if (bm > M) {                        // warp-uniform; rare after warmup
        float sc = exp2f(M - bm);        // first batch: exp2(-inf)=0
        Z *= sc; a0 *= sc; a1 *= sc;
        M = bm;
    }
    float w0 = exp2f(d0 - M);
    float w1 = exp2f(d1 - M);
    float w2 = exp2f(d2 - M);
    float w3 = exp2f(d3 - M);
    float w4 = exp2f(d4 - M);
    float w5 = exp2f(d5 - M);
    float w6 = exp2f(d6 - M);
    float w7 = exp2f(d7 - M);
    Z += ((w0 + w1) + (w2 + w3)) + ((w4 + w5) + (w6 + w7));
    a0 = fmaf(w0, g0.x, a0); a1 = fmaf(w0, g0.y, a1);
    a0 = fmaf(w1, g1.x, a0); a1 = fmaf(w1, g1.y, a1);
    a0 = fmaf(w2, g2.x, a0); a1 = fmaf(w2, g2.y, a1);
    a0 = fmaf(w3, g3.x, a0); a1 = fmaf(w3, g3.y, a1);
    a0 = fmaf(w4, g4.x, a0); a1 = fmaf(w4, g4.y, a1);
    a0 = fmaf(w5, g5.x, a0); a1 = fmaf(w5, g5.y, a1);
    a0 = fmaf(w6, g6.x, a0); a1 = fmaf(w6, g6.y, a1);
    a0 = fmaf(w7, g7.x, a0); a1 = fmaf(w7, g7.y, a1);
}

// ---------------- sparse GAT aggregation (D=64): warp per (b,n) row ----------
// score_nm = fsrc[row] . gsrc[b,m]  (fsrc pre-scaled to exp2 domain here)
// out[row] = softmax-weighted sum of gsrc[b,m] (+bias)
template <bool HAS_BIAS, bool RELU>
__device__ __forceinline__ void agg_body64(const float* __restrict__ fsrc,
                                           const float* __restrict__ gsrc,
                                           const float* __restrict__ bias,
                                           float* __restrict__ out) {
    int warp = threadIdx.x >> 5;
    int lane = threadIdx.x & 31;
    int row = blockIdx.x * 8 + warp;                 // grid exact: B*N/8 blocks
    int n = row & (NNODES - 1);
    const float* hb = gsrc + ((size_t)(row - n) << 6);   // batch base (64-dim rows)
    unsigned loff = (unsigned)lane * 2;

    float2 ft = *(const float2*)(fsrc + ((size_t)row << 6) + loff);
    float f0 = ft.x * LOG2E, f1 = ft.y * LOG2E;      // exp2-domain scores

    float M = -INFINITY, Z = 0.0f, a0 = 0.0f, a1 = 0.0f;
    int deg = d_deg[n];
    const int* cols = d_col + n * CAP;

    int i = 0;
    for (; i + 8 <= deg; i += 8)
        agg_batch<false>(cols, i, 8, hb, loff, f0, f1, M, Z, a0, a1);
    if (i < deg)
        agg_batch<true>(cols, i, deg - i, hb, loff, f0, f1, M, Z, a0, a1);

    float inv = 1.0f / Z;                            // Z >= 1 (max weight = 1)
    float o0 = a0 * inv, o1 = a1 * inv;
    if (HAS_BIAS) { o0 += bias[loff]; o1 += bias[loff + 1]; }
    if (RELU)     { o0 = fmaxf(o0, 0.0f); o1 = fmaxf(o1, 0.0f); }
    *(float2*)(out + ((size_t)row << 6) + loff) = make_float2(o0, o1);
}

__global__ void agg1_kernel(const float* __restrict__ x) {
    // scores via y1 = x G (fsrc = d_h1[0:2M)); values = x; out = c (d_h1[2M:4M))
    agg_body64<false, false>(d_h1, x, nullptr, d_h1 + BATCH * NNODES * DIN0);
}
__global__ void agg2_kernel(const float* __restrict__ b2, float* __restrict__ out) {
    // scores and values both h2 (d_h1[0:2M), written by lin2)
    agg_body64<true, false>(d_h1, d_h1, b2, out);
}

// ---------------- launch ------------------------------------------------------
extern "C" void kernel_launch(void* const* d_in, const int* in_sizes, int n_in,
                              void* d_out, int out_size) {
    const float* flow_x = (const float*)d_in[0];   // [B,N,64]
    const float* graph  = (const float*)d_in[1];   // [N,N]
    const float* W1     = (const float*)d_in[2];   // [128,64]
    const float* b1     = (const float*)d_in[3];   // [128]
    const float* W2     = (const float*)d_in[4];   // [64,128]
    const float* b2     = (const float*)d_in[5];   // [64]
    float*       outp   = (float*)d_out;           // [B,N,1,64]

    // 1) weight transposes + G = W1^T W1 (fused)
    prep_kernel<<<(DHID * DIN0 + 255) / 256, 256>>>(W1, W2);
    // 2) build CSR (shared by both layers & all batches)
    build_csr_kernel<<<NNODES / 8, 256>>>(graph);
    // 3) y1 = x @ G  (64-dim score vectors for layer 1)
    y1_kernel<<<BATCH * NNODES / 8, DIN0>>>(flow_x);
    // 4) layer-1 sparse attention in input space: c = softmax(y1.x) @ x
    agg1_kernel<<<(BATCH * NNODES) / 8, 256>>>(flow_x);
    // 5) t1 = relu(c @ W1^T + b1)
    postlin_kernel<<<BATCH * NNODES / 8, DHID>>>(b1);
    // 6) h2 = t1 @ W2^T
    lin2_kernel<<<BATCH * NNODES / 8, DOUT0>>>();
    // 7) layer-2 sparse attention + bias -> final output
    agg2_kernel<<<(BATCH * NNODES) / 8, 256>>>(b2, outp);
}

// round 12
// speedup vs baseline: 1.0529x; 1.0529x over previous
#include <cuda_runtime.h>
#include <math.h>

// Problem constants
#define BATCH 8
#define NNODES 4096
#define DIN0 64
#define DHID 128
#define DOUT0 64
#define CAP 512          // max neighbors per row (mean ~82 at 2% density; P(>512)~0)

#define LOG2E 1.4426950408889634f
#define NEGBIG (-1.0e30f)

// ---------------- static device scratch (no allocations allowed) -------------
// d_h1 aliasing: [0:2M) = y1 (layer1 score vecs) then h2 (layer2 linear out);
//                [2M:4M) = c (layer1 agg out).
__device__ int   d_col[NNODES * CAP + 8];        // +8 pad (zero-init: node 0 = safe)
__device__ int   d_deg[NNODES];
__device__ float d_h1[BATCH * NNODES * DHID];    // 16 MB, aliased as above
__device__ float d_wt1[DIN0 * DHID];             // W1^T  [k][c]
__device__ float d_wt2[DHID * DOUT0];            // W2^T  [k][c]
__device__ float d_g1[DIN0 * DIN0];              // G = W1^T W1 (64x64)

// ---------------- weight transposes + G = W1^T W1 (fused) --------------------
__global__ void prep_kernel(const float* __restrict__ W1, const float* __restrict__ W2) {
    int i = blockIdx.x * blockDim.x + threadIdx.x;
    if (i < DHID * DIN0) {            // W1: [128][64] -> wt1[k*128 + c]
        int c = i / DIN0, k = i % DIN0;
        d_wt1[k * DHID + c] = W1[i];
    }
    if (i < DOUT0 * DHID) {           // W2: [64][128] -> wt2[k*64 + c]
        int c = i / DHID, k = i % DHID;
        d_wt2[k * DOUT0 + c] = W2[i];
    }
    if (i < DIN0 * DIN0) {            // G[e][d] = sum_h W1[h][d] * W1[h][e]
        int d = i & 63, e = i >> 6;
        float s = 0.0f;
#pragma unroll 4
        for (int h = 0; h < DHID; h++)
            s = fmaf(W1[h * DIN0 + d], W1[h * DIN0 + e], s);
        d_g1[e * DIN0 + d] = s;
    }
}

// ---------------- build CSR from dense binary graph (float4 scan) ------------
// Neighbor order within a row is a fixed permutation of ascending — softmax is
// order-insensitive as a set; only fp rounding order changes.
__global__ void build_csr_kernel(const float* __restrict__ graph) {
    const unsigned FULL = 0xffffffffu;
    int row  = blockIdx.x * (blockDim.x >> 5) + (threadIdx.x >> 5);
    int lane = threadIdx.x & 31;
    const float4* g = (const float4*)(graph + (size_t)row * NNODES);
    unsigned lt = (1u << lane) - 1u;
    int cnt = 0;
    int* outp = d_col + row * CAP;
#pragma unroll 2
    for (int base = 0; base < NNODES / 4; base += 32) {
        float4 v = g[base + lane];
        int col0 = (base + lane) * 4;
        unsigned b;
        b = __ballot_sync(FULL, v.x != 0.0f);
        if (v.x != 0.0f) { int p = cnt + __popc(b & lt); if (p < CAP) outp[p] = col0; }
        cnt += __popc(b);
        b = __ballot_sync(FULL, v.y != 0.0f);
        if (v.y != 0.0f) { int p = cnt + __popc(b & lt); if (p < CAP) outp[p] = col0 + 1; }
        cnt += __popc(b);
        b = __ballot_sync(FULL, v.z != 0.0f);
        if (v.z != 0.0f) { int p = cnt + __popc(b & lt); if (p < CAP) outp[p] = col0 + 2; }
        cnt += __popc(b);
        b = __ballot_sync(FULL, v.w != 0.0f);
        if (v.w != 0.0f) { int p = cnt + __popc(b & lt); if (p < CAP) outp[p] = col0 + 3; }
        cnt += __popc(b);
    }
    if (lane == 0) d_deg[row] = (cnt < CAP) ? cnt : CAP;
}

// ---------------- y1 = x @ G (RPB=8, blockDim=64) ----------------------------
__global__ void y1_kernel(const float* __restrict__ x) {
    constexpr int RPB = 8;
    __shared__ float xs[RPB * DIN0];
    long base = (long)blockIdx.x * RPB;
    const float4* xg  = (const float4*)(x + base * DIN0);
    float4*       xs4 = (float4*)xs;
    for (int i = threadIdx.x; i < RPB * DIN0 / 4; i += blockDim.x) xs4[i] = xg[i];
    __syncthreads();

    int c = threadIdx.x;   // 0..63
    float acc[RPB];
#pragma unroll
    for (int r = 0; r < RPB; r++) acc[r] = 0.0f;
    for (int k = 0; k < DIN0; k += 4) {
        float w0 = d_g1[(k + 0) * DIN0 + c];
        float w1 = d_g1[(k + 1) * DIN0 + c];
        float w2 = d_g1[(k + 2) * DIN0 + c];
        float w3 = d_g1[(k + 3) * DIN0 + c];
#pragma unroll
        for (int r = 0; r < RPB; r++) {
            float4 xv = *(const float4*)&xs[r * DIN0 + k];
            acc[r] = fmaf(xv.x, w0, fmaf(xv.y, w1, fmaf(xv.z, w2, fmaf(xv.w, w3, acc[r]))));
        }
    }
#pragma unroll
    for (int r = 0; r < RPB; r++) d_h1[(base + r) * DIN0 + c] = acc[r];
}

// ---------------- fused MLP: h2 = relu(c @ W1^T + b1) @ W2^T -----------------
// 8 rows per block, 128 threads; t1 lives only in shared memory.
__global__ void mlp_kernel(const float* __restrict__ b1) {
    __shared__ float xs[8 * DIN0];     // staged c rows
    __shared__ float st[8 * DHID];     // t1 rows
    const float* cbase = d_h1 + (size_t)BATCH * NNODES * DIN0;
    long base = (long)blockIdx.x * 8;

    const float4* xg = (const float4*)(cbase + base * DIN0);
    for (int i = threadIdx.x; i < 8 * DIN0 / 4; i += blockDim.x)
        ((float4*)xs)[i] = xg[i];
    __syncthreads();

    // phase A: t1[r][c] = relu(sum_k c[r][k] wt1[k][c] + b1[c])
    int c = threadIdx.x;               // 0..127
    float b = b1[c];
    float acc[8];
#pragma unroll
    for (int r = 0; r < 8; r++) acc[r] = 0.0f;
    for (int k = 0; k < DIN0; k += 4) {
        float w0 = d_wt1[(k + 0) * DHID + c];
        float w1 = d_wt1[(k + 1) * DHID + c];
        float w2 = d_wt1[(k + 2) * DHID + c];
        float w3 = d_wt1[(k + 3) * DHID + c];
#pragma unroll
        for (int r = 0; r < 8; r++) {
            float4 xv = *(const float4*)&xs[r * DIN0 + k];
            acc[r] = fmaf(xv.x, w0, fmaf(xv.y, w1, fmaf(xv.z, w2, fmaf(xv.w, w3, acc[r]))));
        }
    }
#pragma unroll
    for (int r = 0; r < 8; r++) st[r * DHID + c] = fmaxf(acc[r] + b, 0.0f);
    __syncthreads();

    // phase B: h2[r][c2] = sum_k t1[r][k] wt2[k][c2]; thread -> (half, c2)
    int c2 = c & 63, half = c >> 6;    // rows half*4 .. half*4+3
    float o0 = 0.f, o1 = 0.f, o2 = 0.f, o3 = 0.f;
    int r0 = half * 4;
    for (int k = 0; k < DHID; k += 4) {
        float w0 = d_wt2[(k + 0) * DOUT0 + c2];
        float w1 = d_wt2[(k + 1) * DOUT0 + c2];
        float w2 = d_wt2[(k + 2) * DOUT0 + c2];
        float w3 = d_wt2[(k + 3) * DOUT0 + c2];
        float4 x0 = *(const float4*)&st[(r0 + 0) * DHID + k];
        float4 x1 = *(const float4*)&st[(r0 + 1) * DHID + k];
        float4 x2 = *(const float4*)&st[(r0 + 2) * DHID + k];
        float4 x3 = *(const float4*)&st[(r0 + 3) * DHID + k];
        o0 = fmaf(x0.x, w0, fmaf(x0.y, w1, fmaf(x0.z, w2, fmaf(x0.w, w3, o0))));
        o1 = fmaf(x1.x, w0, fmaf(x1.y, w1, fmaf(x1.z, w2, fmaf(x1.w, w3, o1))));
        o2 = fmaf(x2.x, w0, fmaf(x2.y, w1, fmaf(x2.z, w2, fmaf(x2.w, w3, o2))));
        o3 = fmaf(x3.x, w0, fmaf(x3.y, w1, fmaf(x3.z, w2, fmaf(x3.w, w3, o3))));
    }
    d_h1[(base + r0 + 0) * DOUT0 + c2] = o0;
    d_h1[(base + r0 + 1) * DOUT0 + c2] = o1;
    d_h1[(base + r0 + 2) * DOUT0 + c2] = o2;
    d_h1[(base + r0 + 3) * DOUT0 + c2] = o3;
}

// ---------------- sparse GAT aggregation (D=64): 2x16-lane engines -----------
// Each 16-lane group: online softmax over a strided half of the neighbor list,
// 4 neighbors per iteration (8/warp). Merged in-group reduction leaves each
// score replicated on a 4-lane subgroup -> ONE exp2 covers 4 scores. States
// merged at the end (flash combine). M starts at NEGBIG so empty groups give
// zero weight (not NaN).
template <bool HAS_BIAS>
__device__ __forceinline__ void agg_body64(const float* __restrict__ fsrc,
                                           const float* __restrict__ gsrc,
                                           const float* __restrict__ bias,
                                           float* __restrict__ out) {
    const unsigned FULL = 0xffffffffu;
    int warp  = threadIdx.x >> 5;
    int lane  = threadIdx.x & 31;
    int k16   = lane & 15;
    int grp   = lane >> 4;
    int gbase = grp << 4;

    int row = blockIdx.x * 8 + warp;                 // grid exact: B*N/8 blocks
    int n = row & (NNODES - 1);
    const float* hb = gsrc + ((size_t)(row - n) << 6);
    unsigned loff = (unsigned)k16 << 2;              // 4 dims per lane

    float4 ft = *(const float4*)(fsrc + ((size_t)row << 6) + loff);
    float f0 = ft.x * LOG2E, f1 = ft.y * LOG2E;
    float f2 = ft.z * LOG2E, f3 = ft.w * LOG2E;

    float M = NEGBIG, Z = 0.0f;
    float a0 = 0.f, a1 = 0.f, a2 = 0.f, a3 = 0.f;
    int deg = d_deg[n];
    const int* cols = d_col + n * CAP;

    // subgroup (k16>>2) -> neighbor slot j: 0->0, 1->2, 2->1, 3->3
    int sub  = k16 >> 2;
    int jmap = ((sub & 1) << 1) | (sub >> 1);
    int thr  = deg - (grp << 2) - jmap;              // slot valid iff i < thr

    for (int i = 0; i < deg; i += 8) {
        int4 c4 = *(const int4*)(cols + i + (grp << 2));
        float4 g0 = *(const float4*)(hb + (((unsigned)c4.x << 6) + loff));
        float4 g1 = *(const float4*)(hb + (((unsigned)c4.y << 6) + loff));
        float4 g2 = *(const float4*)(hb + (((unsigned)c4.z << 6) + loff));
        float4 g3 = *(const float4*)(hb + (((unsigned)c4.w << 6) + loff));

        float p0 = fmaf(f0, g0.x, fmaf(f1, g0.y, fmaf(f2, g0.z, f3 * g0.w)));
        float p1 = fmaf(f0, g1.x, fmaf(f1, g1.y, fmaf(f2, g1.z, f3 * g1.w)));
        float p2 = fmaf(f0, g2.x, fmaf(f1, g2.y, fmaf(f2, g2.z, f3 * g2.w)));
        float p3 = fmaf(f0, g3.x, fmaf(f1, g3.y, fmaf(f2, g3.z, f3 * g3.w)));

        // merged 4-way reduction within the 16-lane group (5 SHFLs)
        float sA = (k16 & 8) ? p1 : p0, tA = (k16 & 8) ? p0 : p1;
        sA += __shfl_xor_sync(FULL, tA, 8);
        float sB = (k16 & 8) ? p3 : p2, tB = (k16 & 8) ? p2 : p3;
        sB += __shfl_xor_sync(FULL, tB, 8);
        float u  = (k16 & 4) ? sB : sA, ut = (k16 & 4) ? sA : sB;
        u += __shfl_xor_sync(FULL, ut, 4);
        u += __shfl_xor_sync(FULL, u, 2);
        u += __shfl_xor_sync(FULL, u, 1);
        // subgroup holds: base0=d0, base4=d2, base8=d1, base12=d3

        u = (i < thr) ? u : -INFINITY;               // mask invalid slots

        // group max (2 SHFLs)
        float bm = fmaxf(u, __shfl_xor_sync(FULL, u, 4));
        bm = fmaxf(bm, __shfl_xor_sync(FULL, bm, 8));

        if (bm > M) {                                // rare after warmup
            float sc = exp2f(M - bm);
            Z *= sc; a0 *= sc; a1 *= sc; a2 *= sc; a3 *= sc;
            M = bm;
        }
        float w = exp2f(u - M);                      // ONE exp2 for 4 scores

        // Z += sum of the group's 4 weights (2 SHFLs)
        float zs = w + __shfl_xor_sync(FULL, w, 4);
        zs += __shfl_xor_sync(FULL, zs, 8);
        Z += zs;

        // broadcast weights to all group lanes (4 SHFLs)
        float w0 = __shfl_sync(FULL, w, gbase + 0);
        float w1 = __shfl_sync(FULL, w, gbase + 8);
        float w2 = __shfl_sync(FULL, w, gbase + 4);
        float w3 = __shfl_sync(FULL, w, gbase + 12);

        a0 = fmaf(w0, g0.x, a0); a1 = fmaf(w0, g0.y, a1);
        a2 = fmaf(w0, g0.z, a2); a3 = fmaf(w0, g0.w, a3);
        a0 = fmaf(w1, g1.x, a0); a1 = fmaf(w1, g1.y, a1);
        a2 = fmaf(w1, g1.z, a2); a3 = fmaf(w1, g1.w, a3);
        a0 = fmaf(w2, g2.x, a0); a1 = fmaf(w2, g2.y, a1);
        a2 = fmaf(w2, g2.z, a2); a3 = fmaf(w2, g2.w, a3);
        a0 = fmaf(w3, g3.x, a0); a1 = fmaf(w3, g3.y, a1);
        a2 = fmaf(w3, g3.z, a2); a3 = fmaf(w3, g3.w, a3);
    }

    // ---- merge the two groups (flash combine) ----
    float Mo   = __shfl_xor_sync(FULL, M, 16);
    float newM = fmaxf(M, Mo);
    float scl  = exp2f(M - newM);                    // empty group: exp2(-1e30-x)=0
    Z *= scl; a0 *= scl; a1 *= scl; a2 *= scl; a3 *= scl;
    float Zt = Z + __shfl_xor_sync(FULL, Z, 16);
    float b0 = a0 + __shfl_xor_sync(FULL, a0, 16);
    float b1v = a1 + __shfl_xor_sync(FULL, a1, 16);
    float b2 = a2 + __shfl_xor_sync(FULL, a2, 16);
    float b3 = a3 + __shfl_xor_sync(FULL, a3, 16);

    float inv = 1.0f / Zt;                           // Zt >= 1 (max weight = 1)
    float o0 = b0 * inv, o1 = b1v * inv, o2 = b2 * inv, o3 = b3 * inv;
    if (HAS_BIAS) {
        o0 += bias[loff]; o1 += bias[loff + 1];
        o2 += bias[loff + 2]; o3 += bias[loff + 3];
    }
    if (grp == 0)
        *(float4*)(out + ((size_t)row << 6) + loff) = make_float4(o0, o1, o2, o3);
}

__global__ void agg1_kernel(const float* __restrict__ x) {
    // scores via y1 = x G (fsrc = d_h1[0:2M)); values = x; out = c (d_h1[2M:4M))
    agg_body64<false>(d_h1, x, nullptr, d_h1 + (size_t)BATCH * NNODES * DIN0);
}
__global__ void agg2_kernel(const float* __restrict__ b2, float* __restrict__ out) {
    // scores and values both h2 (d_h1[0:2M), written by mlp_kernel)
    agg_body64<true>(d_h1, d_h1, b2, out);
}

// ---------------- launch ------------------------------------------------------
extern "C" void kernel_launch(void* const* d_in, const int* in_sizes, int n_in,
                              void* d_out, int out_size) {
    const float* flow_x = (const float*)d_in[0];   // [B,N,64]
    const float* graph  = (const float*)d_in[1];   // [N,N]
    const float* W1     = (const float*)d_in[2];   // [128,64]
    const float* b1     = (const float*)d_in[3];   // [128]
    const float* W2     = (const float*)d_in[4];   // [64,128]
    const float* b2     = (const float*)d_in[5];   // [64]
    float*       outp   = (float*)d_out;           // [B,N,1,64]

    // 1) weight transposes + G = W1^T W1 (fused)
    prep_kernel<<<(DHID * DIN0 + 255) / 256, 256>>>(W1, W2);
    // 2) build CSR (shared by both layers & all batches)
    build_csr_kernel<<<NNODES / 8, 256>>>(graph);
    // 3) y1 = x @ G  (64-dim score vectors for layer 1)
    y1_kernel<<<BATCH * NNODES / 8, DIN0>>>(flow_x);
    // 4) layer-1 sparse attention in input space: c = softmax(y1.x) @ x
    agg1_kernel<<<(BATCH * NNODES) / 8, 256>>>(flow_x);
    // 5) fused: h2 = relu(c @ W1^T + b1) @ W2^T
    mlp_kernel<<<BATCH * NNODES / 8, 128>>>(b1);
    // 6) layer-2 sparse attention + bias -> final output
    agg2_kernel<<<(BATCH * NNODES) / 8, 256>>>(b2, outp);
}